// round 17
// baseline (speedup 1.0000x reference)
#include <cuda_runtime.h>
#include <cuda_fp16.h>
#include <cstdint>

// Problem constants
#define E_DIM 1024
#define H_DIM 16
#define M_MEM 256
#define B_DIM 2
#define S_DIM 2048
#define D_DIM 64
#define NROWS (B_DIM * S_DIM) /* 4096 */
#define ATT_SCALE 0.125f      /* D^-0.5 */
#define QK_SCALE (0.125f * 1.44269504f) /* D^-0.5 * log2(e): softmax via ex2 */

// -------- scratch (static device globals; no runtime allocation) --------
__device__ __half g_xh[NROWS * E_DIM];
__device__ __half g_Wqh[E_DIM * E_DIM];
__device__ __half g_Wkh[E_DIM * E_DIM];
__device__ __half g_Wvh[E_DIM * E_DIM];
__device__ __half g_Woh[E_DIM * E_DIM];
__device__ __half g_memh[M_MEM * E_DIM];
__device__ __half g_Qh[NROWS * E_DIM];
__device__ __half g_Kh[NROWS * E_DIM];
__device__ __half g_Vh[NROWS * E_DIM];
__device__ float  g_AO[NROWS * E_DIM];
__device__ __half g_MLh[NROWS * M_MEM];   // logits then (in-place) probs
__device__ __half g_MOh[NROWS * E_DIM];

// ---------------------------------------------------------------------------
__device__ __forceinline__ uint32_t exp2_h2(uint32_t x) {
    uint32_t r;
    asm("ex2.approx.f16x2 %0, %1;" : "=r"(r) : "r"(x));
    return r;
}

__device__ __forceinline__ void mma_f16(float c[4], const uint32_t a[4],
                                        const uint32_t b[2]) {
    asm("mma.sync.aligned.m16n8k16.row.col.f32.f16.f16.f32 "
        "{%0,%1,%2,%3}, {%4,%5,%6,%7}, {%8,%9}, {%0,%1,%2,%3};"
        : "+f"(c[0]), "+f"(c[1]), "+f"(c[2]), "+f"(c[3])
        : "r"(a[0]), "r"(a[1]), "r"(a[2]), "r"(a[3]), "r"(b[0]), "r"(b[1]));
}

__device__ __forceinline__ void ldsm_x4(uint32_t r[4], uint32_t addr) {
    asm volatile("ldmatrix.sync.aligned.m8n8.x4.shared.b16 "
                 "{%0,%1,%2,%3}, [%4];"
                 : "=r"(r[0]), "=r"(r[1]), "=r"(r[2]), "=r"(r[3]) : "r"(addr));
}

__device__ __forceinline__ void ldsm_x4_trans(uint32_t r[4], uint32_t addr) {
    asm volatile("ldmatrix.sync.aligned.m8n8.x4.trans.shared.b16 "
                 "{%0,%1,%2,%3}, [%4];"
                 : "=r"(r[0]), "=r"(r[1]), "=r"(r[2]), "=r"(r[3]) : "r"(addr));
}

__device__ __forceinline__ uint32_t pack_h2(float lo, float hi) {
    __half2 h = __floats2half2_rn(lo, hi);
    return *(uint32_t*)&h;
}

__device__ __forceinline__ void cp_async16(void* s, const void* g) {
    uint32_t sa = (uint32_t)__cvta_generic_to_shared(s);
    asm volatile("cp.async.cg.shared.global [%0], [%1], 16;" :: "r"(sa), "l"(g));
}

__device__ __forceinline__ void commit_group() {
    asm volatile("cp.async.commit_group;" ::: "memory");
}

// ---------------------------------------------------------------------------
// Merged fp32 -> fp16 conversion for all six tensors (float4 granularity).
// ---------------------------------------------------------------------------
#define N4_X   (NROWS * E_DIM / 4)   /* 1048576 */
#define N4_W   (E_DIM * E_DIM / 4)   /* 262144 */
#define N4_MEM (M_MEM * E_DIM / 4)   /* 65536 */
#define N4_TOT (N4_X + 4 * N4_W + N4_MEM)

__global__ void __launch_bounds__(256) f2h_all(
    const float* __restrict__ x, const float* __restrict__ wq,
    const float* __restrict__ wk, const float* __restrict__ wv,
    const float* __restrict__ wo, const float* __restrict__ mm,
    __half* __restrict__ xh, __half* __restrict__ wqh,
    __half* __restrict__ wkh, __half* __restrict__ wvh,
    __half* __restrict__ woh, __half* __restrict__ mmh)
{
    int i = blockIdx.x * 256 + threadIdx.x;
    if (i >= N4_TOT) return;
    const float* s; __half* d; int off;
    if (i < N4_X) { s = x; d = xh; off = i; }
    else if (i < N4_X + N4_W) { s = wq; d = wqh; off = i - N4_X; }
    else if (i < N4_X + 2 * N4_W) { s = wk; d = wkh; off = i - N4_X - N4_W; }
    else if (i < N4_X + 3 * N4_W) { s = wv; d = wvh; off = i - N4_X - 2 * N4_W; }
    else if (i < N4_X + 4 * N4_W) { s = wo; d = woh; off = i - N4_X - 3 * N4_W; }
    else { s = mm; d = mmh; off = i - N4_X - 4 * N4_W; }
    float4 v = ((const float4*)s)[off];
    __half2 h0 = __floats2half2_rn(v.x, v.y);
    __half2 h1 = __floats2half2_rn(v.z, v.w);
    uint2 u = {*(uint32_t*)&h0, *(uint32_t*)&h1};
    ((uint2*)d)[off] = u;
}

// ---------------------------------------------------------------------------
// Pipelined fp16 GEMM (K-tile 32, 3-stage cp.async, ldmatrix fragments,
// up to 4 z-batched problems; z==3 may have different N/ldc):
//   C[z] = alpha[z] * (A @ op(B[z]) + bias[z]) (+ Cadd)
// Block tile 128x128x32, 512 threads = 16 warps (4x4), warp tile 32x32.
// ---------------------------------------------------------------------------
#define GH_STAGE 5120                    /* halves per stage per operand */
#define GH_SMEM (3 * 2 * GH_STAGE * 2)   /* 61440 bytes */

template <bool TRANSB, bool HOUT>
__global__ void __launch_bounds__(512) gemm_h(
    const __half* __restrict__ A,
    const __half* __restrict__ B0, const __half* __restrict__ B1,
    const __half* __restrict__ B2, const __half* __restrict__ B3,
    const float* __restrict__ bi0, const float* __restrict__ bi1,
    const float* __restrict__ bi2,
    const float* __restrict__ Cadd,
    void* __restrict__ C0v, void* __restrict__ C1v, void* __restrict__ C2v,
    void* __restrict__ C3v,
    int M, int N, int K, int lda, int ldb, int ldc,
    int N3, int ldc3,
    float a0v, float a1v, float a2v, float a3v)
{
    extern __shared__ __half smhh[];
    __half* As = smhh;                  // [3][128*40]  ([m][k], LD 40 halves)
    __half* Bs = smhh + 3 * GH_STAGE;   // [3][...] TRANSB: [n][k] LD 40; else [k][n] LD 136

    const int z = blockIdx.z;
    const __half* B   = (z == 0) ? B0 : (z == 1) ? B1 : (z == 2) ? B2 : B3;
    const float* bias = (z == 0) ? bi0 : (z == 1) ? bi1 : (z == 2) ? bi2 : nullptr;
    void* Cv          = (z == 0) ? C0v : (z == 1) ? C1v : (z == 2) ? C2v : C3v;
    const float alpha = (z == 0) ? a0v : (z == 1) ? a1v : (z == 2) ? a2v : a3v;
    const int Nz      = (z == 3) ? N3 : N;
    const int ldcz    = (z == 3) ? ldc3 : ldc;

    const int m0 = blockIdx.y * 128, n0 = blockIdx.x * 128;
    if (n0 >= Nz) return;   // whole block exits together (merged small problem)

    const int tid = threadIdx.x;
    const int lane = tid & 31, warp = tid >> 5;
    const int g = lane >> 2, tig = lane & 3;
    const int wm = warp >> 2, wn = warp & 3;

    auto issue = [&](int kt) {
        const int k0 = kt * 32;
        const int buf = kt % 3;
        {
            const int row = tid >> 2, c8 = (tid & 3) * 8;
            cp_async16(&As[buf * GH_STAGE + row * 40 + c8],
                       &A[(long)(m0 + row) * lda + k0 + c8]);
        }
        if (TRANSB) {
            const int row = tid >> 2, c8 = (tid & 3) * 8;
            cp_async16(&Bs[buf * GH_STAGE + row * 40 + c8],
                       &B[(long)(n0 + row) * ldb + k0 + c8]);
        } else {
            const int row = tid >> 4, c8 = (tid & 15) * 8;
            cp_async16(&Bs[buf * GH_STAGE + row * 136 + c8],
                       &B[(long)(k0 + row) * ldb + n0 + c8]);
        }
        commit_group();
    };

    float acc[2][4][4] = {};
    const int nk = K / 32;

    issue(0);
    if (nk > 1) issue(1);

    for (int kt = 0; kt < nk; kt++) {
        if (kt + 2 < nk) {
            issue(kt + 2);
            asm volatile("cp.async.wait_group 2;" ::: "memory");
        } else if (kt + 1 < nk) {
            asm volatile("cp.async.wait_group 1;" ::: "memory");
        } else {
            asm volatile("cp.async.wait_group 0;" ::: "memory");
        }
        __syncthreads();

        const __half* Ab = As + (kt % 3) * GH_STAGE;
        const __half* Bb = Bs + (kt % 3) * GH_STAGE;
        const uint32_t ab = (uint32_t)__cvta_generic_to_shared(Ab);
        const uint32_t bb = (uint32_t)__cvta_generic_to_shared(Bb);

#pragma unroll
        for (int ks = 0; ks < 32; ks += 16) {
            uint32_t af[2][4];
#pragma unroll
            for (int mi = 0; mi < 2; mi++) {
                const uint32_t ra = (uint32_t)(wm * 32 + mi * 16 + (lane & 15));
                ldsm_x4(af[mi], ab + (ra * 40 + ks + (lane >> 4) * 8) * 2);
            }
            if (TRANSB) {
#pragma unroll
                for (int np = 0; np < 2; np++) {
                    uint32_t r4[4];
                    const uint32_t rb = (uint32_t)(wn * 32 + np * 16
                                       + (lane & 7) + (lane >> 4) * 8);
                    ldsm_x4(r4, bb + (rb * 40 + ks + ((lane >> 3) & 1) * 8) * 2);
                    uint32_t b0[2] = {r4[0], r4[1]};
                    uint32_t b1[2] = {r4[2], r4[3]};
#pragma unroll
                    for (int mi = 0; mi < 2; mi++) {
                        mma_f16(acc[mi][np * 2], af[mi], b0);
                        mma_f16(acc[mi][np * 2 + 1], af[mi], b1);
                    }
                }
            } else {
#pragma unroll
                for (int np = 0; np < 2; np++) {
                    uint32_t r4[4];
                    ldsm_x4_trans(r4, bb + (ks + (lane & 15)) * 272
                                     + (wn * 32 + np * 16) * 2
                                     + (lane >> 4) * 16);
                    uint32_t b0[2] = {r4[0], r4[1]};
                    uint32_t b1[2] = {r4[2], r4[3]};
#pragma unroll
                    for (int mi = 0; mi < 2; mi++) {
                        mma_f16(acc[mi][np * 2], af[mi], b0);
                        mma_f16(acc[mi][np * 2 + 1], af[mi], b1);
                    }
                }
            }
        }
        __syncthreads();
    }

    // ---- epilogue: C = alpha*(acc + bias) (+ Cadd) ----
#pragma unroll
    for (int mi = 0; mi < 2; mi++) {
#pragma unroll
        for (int ni = 0; ni < 4; ni++) {
            const int m = m0 + wm * 32 + mi * 16 + g;
            const int n = n0 + wn * 32 + ni * 8 + tig * 2;
            float b0 = 0.f, b1 = 0.f;
            if (bias) { b0 = bias[n]; b1 = bias[n + 1]; }
            float o0x = (acc[mi][ni][0] + b0) * alpha;
            float o0y = (acc[mi][ni][1] + b1) * alpha;
            float o1x = (acc[mi][ni][2] + b0) * alpha;
            float o1y = (acc[mi][ni][3] + b1) * alpha;
            if (Cadd) {
                float2 a0 = *(const float2*)&Cadd[(long)m * ldcz + n];
                float2 a1 = *(const float2*)&Cadd[(long)(m + 8) * ldcz + n];
                o0x += a0.x; o0y += a0.y;
                o1x += a1.x; o1y += a1.y;
            }
            if (HOUT) {
                __half* Ch = (__half*)Cv;
                *(__half2*)&Ch[(long)m * ldcz + n] = __floats2half2_rn(o0x, o0y);
                *(__half2*)&Ch[(long)(m + 8) * ldcz + n] = __floats2half2_rn(o1x, o1y);
            } else {
                float* C = (float*)Cv;
                float2 q0 = {o0x, o0y}, q1 = {o1x, o1y};
                *(float2*)&C[(long)m * ldcz + n]       = q0;
                *(float2*)&C[(long)(m + 8) * ldcz + n] = q1;
            }
        }
    }
}

// ---------------------------------------------------------------------------
// Fused flash attention v6 (fp16 MMA, ldmatrix frags, 3-stage pipeline,
// f16x2 exp: pack logits to half2 first, then one ex2.approx.f16x2 each).
// Per block: one (b,h), 128-query tile; 256 thr = 8 warps, warp owns 16 rows.
// ---------------------------------------------------------------------------
#define FA_BR 128
#define FA_BC 64
#define LDH 72
#define FA_NT (S_DIM / FA_BC)
#define FA_TILE (FA_BC * LDH)
#define FA_SMEM (6 * FA_TILE * 2)   /* 3 bufs x (K+V) = 55296 bytes */

__global__ void __launch_bounds__(256, 2) flash_attn(
    const __half* __restrict__ Q, const __half* __restrict__ K,
    const __half* __restrict__ V, float* __restrict__ O)
{
    extern __shared__ __half smh[];
    __half* Ks = smh;                 // [3][FA_BC][LDH]
    __half* Vs = smh + 3 * FA_TILE;   // [3][FA_BC][LDH]

    const int bh = blockIdx.y;
    const int b = bh / H_DIM, h = bh % H_DIM;
    const int s0 = blockIdx.x * FA_BR;

    const long base = (long)b * S_DIM * E_DIM + h * D_DIM;
    const __half* Qb = Q + base;
    const __half* Kb = K + base;
    const __half* Vb = V + base;
    float* Ob = O + base;

    const int tid = threadIdx.x;
    const int lane = tid & 31, warp = tid >> 5;
    const int g = lane >> 2, tig = lane & 3;
    const int r0 = warp * 16;

    uint32_t qf[4][4];
    {
        const __half* Qw = Qb + (long)(s0 + r0) * E_DIM;
#pragma unroll
        for (int ks = 0; ks < 4; ks++) {
            qf[ks][0] = *(const uint32_t*)&Qw[(long)g * E_DIM + ks * 16 + tig * 2];
            qf[ks][1] = *(const uint32_t*)&Qw[(long)(g + 8) * E_DIM + ks * 16 + tig * 2];
            qf[ks][2] = *(const uint32_t*)&Qw[(long)g * E_DIM + ks * 16 + tig * 2 + 8];
            qf[ks][3] = *(const uint32_t*)&Qw[(long)(g + 8) * E_DIM + ks * 16 + tig * 2 + 8];
        }
    }

    float oacc[8][4] = {};
    float lA = 0.f, lB = 0.f;

    auto issue = [&](int jt) {
        const int bufi = jt % 3;
        const __half* Kg = Kb + (long)jt * FA_BC * E_DIM;
        const __half* Vg = Vb + (long)jt * FA_BC * E_DIM;
        __half* Kd = Ks + bufi * FA_TILE;
        __half* Vd = Vs + bufi * FA_TILE;
#pragma unroll
        for (int t = 0; t < 2; t++) {
            const int c = tid + t * 256;
            const int row = c >> 3, ch = (c & 7) * 8;
            cp_async16(&Kd[row * LDH + ch], &Kg[(long)row * E_DIM + ch]);
        }
#pragma unroll
        for (int t = 0; t < 2; t++) {
            const int c = tid + t * 256;
            const int row = c >> 3, ch = (c & 7) * 8;
            cp_async16(&Vd[row * LDH + ch], &Vg[(long)row * E_DIM + ch]);
        }
        commit_group();
    };

    issue(0);
    issue(1);

    for (int jt = 0; jt < FA_NT; jt++) {
        const int buf = jt % 3;
        if (jt + 2 < FA_NT) {
            issue(jt + 2);
            asm volatile("cp.async.wait_group 2;" ::: "memory");
        } else if (jt + 1 < FA_NT) {
            asm volatile("cp.async.wait_group 1;" ::: "memory");
        } else {
            asm volatile("cp.async.wait_group 0;" ::: "memory");
        }
        __syncthreads();

        const __half* KsB = Ks + buf * FA_TILE;
        const __half* VsB = Vs + buf * FA_TILE;
        const uint32_t kb = (uint32_t)__cvta_generic_to_shared(KsB);

        // ---- S' = Qscaled @ K^T : K B-frags via ldmatrix.x4 ----
        float sacc[8][4] = {};
#pragma unroll
        for (int ks = 0; ks < 4; ks++) {
#pragma unroll
            for (int np = 0; np < 4; np++) {
                uint32_t r4[4];
                const uint32_t rk = (uint32_t)(np * 16 + (lane & 7)
                                   + (lane >> 4) * 8);
                ldsm_x4(r4, kb + (rk * LDH + ks * 16 + ((lane >> 3) & 1) * 8) * 2);
                uint32_t b0[2] = {r4[0], r4[1]};
                uint32_t b1[2] = {r4[2], r4[3]};
                mma_f16(sacc[np * 2], qf[ks], b0);
                mma_f16(sacc[np * 2 + 1], qf[ks], b1);
            }
        }

        // ---- p = 2^(s') in fp16x2: pack logits, single ex2 per pair ----
        uint32_t pf[8][2];
#pragma unroll
        for (int ni = 0; ni < 8; ni++) {
            pf[ni][0] = exp2_h2(pack_h2(sacc[ni][0], sacc[ni][1]));  // row g
            pf[ni][1] = exp2_h2(pack_h2(sacc[ni][2], sacc[ni][3]));  // row g+8
            float2 fa = __half22float2(*(__half2*)&pf[ni][0]);
            float2 fb = __half22float2(*(__half2*)&pf[ni][1]);
            lA += fa.x + fa.y;
            lB += fb.x + fb.y;
        }

        // ---- O += P @ V : pf IS the A-fragment; V via ldmatrix.trans ----
        const uint32_t vbase = (uint32_t)__cvta_generic_to_shared(VsB);
        const uint32_t vrow = (lane & 15) * (LDH * 2);
        const uint32_t vcol = (lane >> 4) * 16;
#pragma unroll
        for (int kp = 0; kp < 4; kp++) {
            uint32_t af[4];
            af[0] = pf[2 * kp][0];
            af[1] = pf[2 * kp][1];
            af[2] = pf[2 * kp + 1][0];
            af[3] = pf[2 * kp + 1][1];
#pragma unroll
            for (int np = 0; np < 4; np++) {
                uint32_t r[4];
                ldsm_x4_trans(r, vbase + (kp * 16) * (LDH * 2) + vrow
                                 + np * 32 + vcol);
                uint32_t b0[2] = {r[0], r[1]};
                uint32_t b1[2] = {r[2], r[3]};
                mma_f16(oacc[np * 2], af, b0);
                mma_f16(oacc[np * 2 + 1], af, b1);
            }
        }
        __syncthreads();
    }

    lA += __shfl_xor_sync(0xffffffff, lA, 1);
    lA += __shfl_xor_sync(0xffffffff, lA, 2);
    lB += __shfl_xor_sync(0xffffffff, lB, 1);
    lB += __shfl_xor_sync(0xffffffff, lB, 2);
    const float invA = 1.0f / lA, invB = 1.0f / lB;
#pragma unroll
    for (int ni = 0; ni < 8; ni++) {
        const int col = ni * 8 + tig * 2;
        const int rA = s0 + r0 + g, rB = rA + 8;
        float2 oa = {oacc[ni][0] * invA, oacc[ni][1] * invA};
        float2 ob = {oacc[ni][2] * invB, oacc[ni][3] * invB};
        *(float2*)&Ob[(long)rA * E_DIM + col] = oa;
        *(float2*)&Ob[(long)rB * E_DIM + col] = ob;
    }
}

// ---------------------------------------------------------------------------
// Warp-per-row softmax, in-place on fp16 logits -> fp16 probs. 8 rows/block.
// ---------------------------------------------------------------------------
__global__ void __launch_bounds__(256) softmax_warp(__half* __restrict__ data)
{
    const int warp = threadIdx.x >> 5, lane = threadIdx.x & 31;
    __half2* p2 = (__half2*)(data + ((long)blockIdx.x * 8 + warp) * M_MEM);

    float v[8];
    float mx = -1e30f;
#pragma unroll
    for (int i = 0; i < 4; i++) {
        float2 f = __half22float2(p2[lane + i * 32]);
        v[2 * i] = f.x; v[2 * i + 1] = f.y;
        mx = fmaxf(mx, fmaxf(f.x, f.y));
    }
#pragma unroll
    for (int o = 16; o > 0; o >>= 1)
        mx = fmaxf(mx, __shfl_xor_sync(0xffffffff, mx, o));

    float s = 0.f;
#pragma unroll
    for (int i = 0; i < 8; i++) {
        v[i] = __expf(v[i] - mx);
        s += v[i];
    }
#pragma unroll
    for (int o = 16; o > 0; o >>= 1)
        s += __shfl_xor_sync(0xffffffff, s, o);

    const float inv = 1.0f / s;
#pragma unroll
    for (int i = 0; i < 4; i++)
        p2[lane + i * 32] = __floats2half2_rn(v[2 * i] * inv, v[2 * i + 1] * inv);
}

// ---------------------------------------------------------------------------
extern "C" void kernel_launch(void* const* d_in, const int* in_sizes, int n_in,
                              void* d_out, int out_size)
{
    const float* x   = (const float*)d_in[0];
    const float* Wq  = (const float*)d_in[1];
    const float* bq  = (const float*)d_in[2];
    const float* Wk  = (const float*)d_in[3];
    const float* bk  = (const float*)d_in[4];
    const float* Wv  = (const float*)d_in[5];
    const float* bv  = (const float*)d_in[6];
    const float* Wo  = (const float*)d_in[7];
    const float* bo  = (const float*)d_in[8];
    const float* mem = (const float*)d_in[9];
    float* out = (float*)d_out;

    __half *xh, *Wqh, *Wkh, *Wvh, *Woh, *memh, *Qh, *Kh, *Vh, *MLh, *MOh;
    float *AO;
    cudaGetSymbolAddress((void**)&xh, g_xh);
    cudaGetSymbolAddress((void**)&Wqh, g_Wqh);
    cudaGetSymbolAddress((void**)&Wkh, g_Wkh);
    cudaGetSymbolAddress((void**)&Wvh, g_Wvh);
    cudaGetSymbolAddress((void**)&Woh, g_Woh);
    cudaGetSymbolAddress((void**)&memh, g_memh);
    cudaGetSymbolAddress((void**)&Qh, g_Qh);
    cudaGetSymbolAddress((void**)&Kh, g_Kh);
    cudaGetSymbolAddress((void**)&Vh, g_Vh);
    cudaGetSymbolAddress((void**)&AO, g_AO);
    cudaGetSymbolAddress((void**)&MLh, g_MLh);
    cudaGetSymbolAddress((void**)&MOh, g_MOh);

    cudaFuncSetAttribute(flash_attn,
        cudaFuncAttributeMaxDynamicSharedMemorySize, FA_SMEM);
    cudaFuncSetAttribute(gemm_h<true, true>,
        cudaFuncAttributeMaxDynamicSharedMemorySize, GH_SMEM);
    cudaFuncSetAttribute(gemm_h<true, false>,
        cudaFuncAttributeMaxDynamicSharedMemorySize, GH_SMEM);
    cudaFuncSetAttribute(gemm_h<false, true>,
        cudaFuncAttributeMaxDynamicSharedMemorySize, GH_SMEM);

    dim3 blk(512);

    // 0) fp32 -> fp16 conversions (single merged launch)
    f2h_all<<<(N4_TOT + 255) / 256, 256>>>(x, Wq, Wk, Wv, Wo, mem,
                                           xh, Wqh, Wkh, Wvh, Woh, memh);

    // 1) QKV projections + memory logits, one z=4 launch.
    //    z0..2: [4096,1024] = x @ W^T + b -> fp16 (Q pre-scaled)
    //    z3:    [4096, 256] = ATT_SCALE * x @ mem^T -> fp16 logits
    {
        dim3 grid(E_DIM / 128, NROWS / 128, 4);
        gemm_h<true, true><<<grid, blk, GH_SMEM>>>(xh, Wqh, Wkh, Wvh, memh,
            bq, bk, bv, nullptr, Qh, Kh, Vh, MLh,
            NROWS, E_DIM, E_DIM, E_DIM, E_DIM, E_DIM,
            M_MEM, M_MEM,
            QK_SCALE, 1.0f, 1.0f, ATT_SCALE);
    }

    // 2) fused flash attention -> AO (fp32, [b,s,e] layout)
    {
        dim3 grid(S_DIM / FA_BR, B_DIM * H_DIM);
        flash_attn<<<grid, dim3(256), FA_SMEM>>>(Qh, Kh, Vh, AO);
    }

    // 3) softmax over memory slots (in-place fp16)
    softmax_warp<<<NROWS / 8, dim3(256)>>>(MLh);

    // 4) combined: MOh = fp16(AO + 0.5 * (P_mem @ mem))
    {
        dim3 grid(E_DIM / 128, NROWS / 128, 1);
        gemm_h<false, true><<<grid, blk, GH_SMEM>>>(MLh, memh, memh, memh, memh,
            nullptr, nullptr, nullptr, AO, MOh, MOh, MOh, MOh,
            NROWS, E_DIM, M_MEM, M_MEM, E_DIM, E_DIM,
            E_DIM, E_DIM,
            0.5f, 0.5f, 0.5f, 0.5f);
    }

    // 5) final: out = MO @ Wo^T + bo (fp32 out)
    {
        dim3 grid(E_DIM / 128, NROWS / 128, 1);
        gemm_h<true, false><<<grid, blk, GH_SMEM>>>(MOh, Woh, Woh, Woh, Woh,
            bo, bo, bo, nullptr, out, out, out, out,
            NROWS, E_DIM, E_DIM, E_DIM, E_DIM, E_DIM,
            E_DIM, E_DIM,
            1.0f, 1.0f, 1.0f, 1.0f);
    }
}